// round 7
// baseline (speedup 1.0000x reference)
#include <cuda_runtime.h>
#include <math.h>

#define NN   30000
#define FIN  500
#define HIDN 16
#define OUTC 3
#define NE   960000

typedef unsigned long long ull;

// ---------------- scratch (device globals: no allocation allowed) ----------------
__device__ float g_h0[NN * HIDN];    // pooled conv features
__device__ float g_m1[NN * HIDN];    // (h0 @ W1) * dinv
__device__ float g_acc1[NN * HIDN];  // scatter accumulator layer 1
__device__ float g_m2[NN * 4];       // (out1 @ W2) * dinv (padded to 4)
__device__ float g_acc2[NN * 4];     // scatter accumulator layer 2
__device__ float g_dinv[NN];
__device__ int   g_deg[NN];

// ---------------- packed fp32x2 helpers (FFMA2 — PTX only) ----------------
__device__ __forceinline__ ull fma2(ull a, ull b, ull c) {
    ull d;
    asm("fma.rn.f32x2 %0, %1, %2, %3;" : "=l"(d) : "l"(a), "l"(b), "l"(c));
    return d;
}
__device__ __forceinline__ ull add2(ull a, ull b) {
    ull d;
    asm("add.rn.f32x2 %0, %1, %2;" : "=l"(d) : "l"(a), "l"(b));
    return d;
}
__device__ __forceinline__ void red4(float* p, float4 v) {
    asm volatile("red.global.add.v4.f32 [%0], {%1,%2,%3,%4};"
                 :: "l"(p), "f"(v.x), "f"(v.y), "f"(v.z), "f"(v.w) : "memory");
}

// ---------------- fused conv1+relu+conv2+relu+maxpool ----------------
// One block = one node. 128 threads = 8 half-warp "sets"; within a set the 16
// lanes each own one output channel o and all read the SAME y1 column
// (SMEM broadcast). Sliding 3-column window in registers; weights packed as
// f32x2 channel-pairs in registers.
__global__ void __launch_bounds__(128) conv_fused_kernel(
    const float* __restrict__ x,
    const float* __restrict__ w1, const float* __restrict__ b1,
    const float* __restrict__ w2, const float* __restrict__ b2)
{
    __shared__ __align__(16) float xs[FIN + 4];                // 1-based, zero pads at 0 and FIN+1
    __shared__ __align__(16) float y1s[(FIN + 2) * HIDN];      // [P][i], P=0..501, cols 0/501 zero
    __shared__ __align__(8)  float2 w2p[HIDN * 24];            // [o][tap*8 + i2] = {w[o][2*i2][tap], w[o][2*i2+1][tap]}
    __shared__ float redbuf[128];

    const int t = threadIdx.x;
    const int node = blockIdx.x;

    // load x row (500 floats = 125 float4; node*2000B is 16B-aligned)
    if (t < 125) {
        float4 v = reinterpret_cast<const float4*>(x + node * FIN)[t];
        xs[1 + 4 * t + 0] = v.x; xs[1 + 4 * t + 1] = v.y;
        xs[1 + 4 * t + 2] = v.z; xs[1 + 4 * t + 3] = v.w;
    }
    if (t == 0) { xs[0] = 0.f; xs[FIN + 1] = 0.f; }
    if (t < HIDN) { y1s[t] = 0.f; y1s[(FIN + 1) * HIDN + t] = 0.f; }

    // pack conv2 weights into f32x2 channel pairs
    for (int idx = t; idx < HIDN * 24; idx += 128) {
        int o = idx / 24, r = idx % 24, tap = r >> 3, i2 = r & 7;
        w2p[idx] = make_float2(w2[o * 48 + (2 * i2) * 3 + tap],
                               w2[o * 48 + (2 * i2 + 1) * 3 + tap]);
    }

    const int ci = t & 15;  // constant per thread across the conv1 strided loop
    const float cw0 = __ldg(w1 + ci * 3 + 0);
    const float cw1 = __ldg(w1 + ci * 3 + 1);
    const float cw2 = __ldg(w1 + ci * 3 + 2);
    const float cb  = __ldg(b1 + ci);
    __syncthreads();

    // ---- conv1 + relu -> y1s[p+1][ci] ----
    for (int idx = t; idx < FIN * HIDN; idx += 128) {
        int p = idx >> 4;  // 0..499
        float v = fmaf(cw0, xs[p], fmaf(cw1, xs[p + 1], fmaf(cw2, xs[p + 2], cb)));
        y1s[(p + 1) * HIDN + ci] = fmaxf(v, 0.f);
    }
    __syncthreads();

    // ---- conv2 + relu + max over positions ----
    const int o      = t & 15;
    const int set    = t >> 4;           // 0..7
    const int pstart = set * 63;
    const int pend   = (pstart + 63 < FIN) ? (pstart + 63) : FIN;  // last set = 59

    ull wv[24];
    {
        const ull* wp = reinterpret_cast<const ull*>(w2p) + o * 24;
        #pragma unroll
        for (int j = 0; j < 24; j++) wv[j] = wp[j];
    }

    ull c0[8], c1[8], c2[8];
    float mx = -3.4e38f;

    auto loadcol = [&](ull (&c)[8], int P) {
        const ulonglong2* cp = reinterpret_cast<const ulonglong2*>(y1s + P * HIDN);
        ulonglong2 a = cp[0], b = cp[1], cc = cp[2], d = cp[3];
        c[0] = a.x; c[1] = a.y; c[2] = b.x; c[3] = b.y;
        c[4] = cc.x; c[5] = cc.y; c[6] = d.x; c[7] = d.y;
    };
    auto step = [&](ull (&A)[8], ull (&B)[8], ull (&C)[8]) {
        ull a0 = 0, a1 = 0, a2 = 0;  // 3 independent chains
        #pragma unroll
        for (int j = 0; j < 8; j++) {
            a0 = fma2(wv[j],      A[j], a0);
            a1 = fma2(wv[8 + j],  B[j], a1);
            a2 = fma2(wv[16 + j], C[j], a2);
        }
        ull sv = add2(add2(a0, a1), a2);
        float lo = __uint_as_float((unsigned)(sv & 0xffffffffull));
        float hi = __uint_as_float((unsigned)(sv >> 32));
        mx = fmaxf(mx, lo + hi);
    };

    // position p needs smem columns p, p+1, p+2 (1-based layout)
    loadcol(c0, pstart);
    loadcol(c1, pstart + 1);
    int p = pstart;
    const int ntrip = (pend - pstart) / 3;
    for (int it = 0; it < ntrip; it++) {
        loadcol(c2, p + 2); step(c0, c1, c2);
        loadcol(c0, p + 3); step(c1, c2, c0);
        loadcol(c1, p + 4); step(c2, c0, c1);
        p += 3;
    }
    for (; p < pend; p++) {  // scalar remainder (<=2 positions)
        float s = 0.f;
        #pragma unroll
        for (int j = 0; j < 24; j++) {
            float2 w = w2p[o * 24 + j];
            int tap = j >> 3, i2 = j & 7;
            s += w.x * y1s[(p + tap) * HIDN + 2 * i2]
               + w.y * y1s[(p + tap) * HIDN + 2 * i2 + 1];
        }
        mx = fmaxf(mx, s);
    }

    // cross-set max reduction; relu(b + max) == max_p relu(b + s_p)
    redbuf[t] = mx;
    __syncthreads();
    if (t < HIDN) {
        float m = redbuf[t];
        #pragma unroll
        for (int s2 = 1; s2 < 8; s2++) m = fmaxf(m, redbuf[t + 16 * s2]);
        g_h0[node * HIDN + t] = fmaxf(m + __ldg(b2 + t), 0.f);
    }
}

// ---------------- GCN kernels ----------------
__global__ void zero_kernel() {
    int i = blockIdx.x * blockDim.x + threadIdx.x;
    if (i < NN * HIDN) g_acc1[i] = 0.f;
    if (i < NN * 4)    g_acc2[i] = 0.f;
    if (i < NN)        g_deg[i]  = 0;
}

__global__ void deg_kernel(const int* __restrict__ ei) {
    int e = blockIdx.x * blockDim.x + threadIdx.x;
    if (e < NE) atomicAdd(&g_deg[ei[NE + e]], 1);
}

// m1[v][j] = dinv[v] * sum_i h0[v][i] * W1[i][j]
__global__ void m1_kernel(const float* __restrict__ w) {
    int gid = blockIdx.x * blockDim.x + threadIdx.x;
    if (gid >= NN * HIDN) return;
    int v = gid >> 4, j = gid & 15;
    float dinv = rsqrtf((float)g_deg[v] + 1.0f);   // +1 self-loop
    if (j == 0) g_dinv[v] = dinv;
    float s = 0.f;
    #pragma unroll
    for (int i = 0; i < HIDN; i++)
        s = fmaf(g_h0[v * HIDN + i], __ldg(w + i * HIDN + j), s);
    g_m1[gid] = s * dinv;
}

__global__ void scatter1_kernel(const int* __restrict__ ei) {
    int e = blockIdx.x * blockDim.x + threadIdx.x;
    if (e >= NE) return;
    int s = ei[e], d = ei[NE + e];
    const float4* m = reinterpret_cast<const float4*>(g_m1 + s * HIDN);
    float4 v0 = m[0], v1 = m[1], v2 = m[2], v3 = m[3];
    float* a = g_acc1 + d * HIDN;
    red4(a, v0); red4(a + 4, v1); red4(a + 8, v2); red4(a + 12, v3);
}

// out1 = relu(dinv*(acc1+m1) + b1g); m2 = (out1 @ W2g) * dinv
__global__ void out1m2_kernel(const float* __restrict__ gb1, const float* __restrict__ gw2) {
    int v = blockIdx.x * blockDim.x + threadIdx.x;
    if (v >= NN) return;
    float dinv = g_dinv[v];
    const float4* a = reinterpret_cast<const float4*>(g_acc1 + v * HIDN);
    const float4* m = reinterpret_cast<const float4*>(g_m1 + v * HIDN);
    float o1[HIDN];
    #pragma unroll
    for (int q = 0; q < 4; q++) {
        float4 av = a[q], mv = m[q];
        o1[4 * q + 0] = fmaxf(dinv * (av.x + mv.x) + __ldg(gb1 + 4 * q + 0), 0.f);
        o1[4 * q + 1] = fmaxf(dinv * (av.y + mv.y) + __ldg(gb1 + 4 * q + 1), 0.f);
        o1[4 * q + 2] = fmaxf(dinv * (av.z + mv.z) + __ldg(gb1 + 4 * q + 2), 0.f);
        o1[4 * q + 3] = fmaxf(dinv * (av.w + mv.w) + __ldg(gb1 + 4 * q + 3), 0.f);
    }
    float s0 = 0.f, s1 = 0.f, s2 = 0.f;
    #pragma unroll
    for (int j = 0; j < HIDN; j++) {
        float h = o1[j];
        s0 = fmaf(h, __ldg(gw2 + j * 3 + 0), s0);
        s1 = fmaf(h, __ldg(gw2 + j * 3 + 1), s1);
        s2 = fmaf(h, __ldg(gw2 + j * 3 + 2), s2);
    }
    reinterpret_cast<float4*>(g_m2)[v] = make_float4(s0 * dinv, s1 * dinv, s2 * dinv, 0.f);
}

__global__ void scatter2_kernel(const int* __restrict__ ei) {
    int e = blockIdx.x * blockDim.x + threadIdx.x;
    if (e >= NE) return;
    int s = ei[e], d = ei[NE + e];
    float4 v = reinterpret_cast<const float4*>(g_m2)[s];
    red4(g_acc2 + d * 4, v);
}

__global__ void final_kernel(const float* __restrict__ gb2, float* __restrict__ out) {
    int v = blockIdx.x * blockDim.x + threadIdx.x;
    if (v >= NN) return;
    float dinv = g_dinv[v];
    float4 a = reinterpret_cast<const float4*>(g_acc2)[v];
    float4 m = reinterpret_cast<const float4*>(g_m2)[v];
    float z0 = dinv * (a.x + m.x) + __ldg(gb2 + 0);
    float z1 = dinv * (a.y + m.y) + __ldg(gb2 + 1);
    float z2 = dinv * (a.z + m.z) + __ldg(gb2 + 2);
    float mx = fmaxf(z0, fmaxf(z1, z2));
    float l = logf(expf(z0 - mx) + expf(z1 - mx) + expf(z2 - mx));
    out[v * 3 + 0] = z0 - mx - l;
    out[v * 3 + 1] = z1 - mx - l;
    out[v * 3 + 2] = z2 - mx - l;
}

// ---------------- launch ----------------
extern "C" void kernel_launch(void* const* d_in, const int* in_sizes, int n_in,
                              void* d_out, int out_size) {
    const float* x   = (const float*)d_in[0];
    const float* c1w = (const float*)d_in[1];
    const float* c1b = (const float*)d_in[2];
    const float* c2w = (const float*)d_in[3];
    const float* c2b = (const float*)d_in[4];
    const float* g1w = (const float*)d_in[5];
    const float* g1b = (const float*)d_in[6];
    const float* g2w = (const float*)d_in[7];
    const float* g2b = (const float*)d_in[8];
    const int*   ei  = (const int*)d_in[9];
    float* out = (float*)d_out;

    zero_kernel<<<(NN * HIDN + 255) / 256, 256>>>();
    conv_fused_kernel<<<NN, 128>>>(x, c1w, c1b, c2w, c2b);
    deg_kernel<<<(NE + 255) / 256, 256>>>(ei);
    m1_kernel<<<(NN * HIDN + 255) / 256, 256>>>(g1w);
    scatter1_kernel<<<(NE + 255) / 256, 256>>>(ei);
    out1m2_kernel<<<(NN + 127) / 128, 128>>>(g1b, g2w);
    scatter2_kernel<<<(NE + 255) / 256, 256>>>(ei);
    final_kernel<<<(NN + 127) / 128, 128>>>(g2b, out);
}

// round 8
// speedup vs baseline: 1.0068x; 1.0068x over previous
#include <cuda_runtime.h>
#include <math.h>

#define NN   30000
#define FIN  500
#define HIDN 16
#define OUTC 3
#define NE   960000

typedef unsigned long long ull;

// ---------------- scratch (device globals: no allocation allowed) ----------------
__device__ float g_h0[NN * HIDN];    // pooled conv features
__device__ float g_m1[NN * HIDN];    // (h0 @ W1) * dinv
__device__ float g_acc1[NN * HIDN];  // scatter accumulator layer 1
__device__ float g_m2[NN * 4];       // (out1 @ W2) * dinv (padded to 4)
__device__ float g_acc2[NN * 4];     // scatter accumulator layer 2
__device__ float g_dinv[NN];
__device__ int   g_deg[NN];

// ---------------- packed fp32x2 helpers (FFMA2 — PTX only) ----------------
__device__ __forceinline__ ull fma2(ull a, ull b, ull c) {
    ull d;
    asm("fma.rn.f32x2 %0, %1, %2, %3;" : "=l"(d) : "l"(a), "l"(b), "l"(c));
    return d;
}
__device__ __forceinline__ ull add2(ull a, ull b) {
    ull d;
    asm("add.rn.f32x2 %0, %1, %2;" : "=l"(d) : "l"(a), "l"(b));
    return d;
}
__device__ __forceinline__ void red4(float* p, float4 v) {
    asm volatile("red.global.add.v4.f32 [%0], {%1,%2,%3,%4};"
                 :: "l"(p), "f"(v.x), "f"(v.y), "f"(v.z), "f"(v.w) : "memory");
}

// ---------------- fused conv1+relu+conv2+relu+maxpool ----------------
// One block = one node. 128 threads = 8 half-warp "sets"; within a set the 16
// lanes each own one output channel o and all read the SAME y1 column
// (SMEM broadcast). Sliding 3-column window in registers; weights packed as
// f32x2 channel-pairs in registers.
__global__ void __launch_bounds__(128) conv_fused_kernel(
    const float* __restrict__ x,
    const float* __restrict__ w1, const float* __restrict__ b1,
    const float* __restrict__ w2, const float* __restrict__ b2)
{
    __shared__ __align__(16) float xs[FIN + 4];                // 1-based, zero pads at 0 and FIN+1
    __shared__ __align__(16) float y1s[(FIN + 2) * HIDN];      // [P][i], P=0..501, cols 0/501 zero
    __shared__ __align__(8)  float2 w2p[HIDN * 24];            // [o][tap*8 + i2] = {w[o][2*i2][tap], w[o][2*i2+1][tap]}
    __shared__ float redbuf[128];

    const int t = threadIdx.x;
    const int node = blockIdx.x;

    // load x row (500 floats = 125 float4; node*2000B is 16B-aligned)
    if (t < 125) {
        float4 v = reinterpret_cast<const float4*>(x + node * FIN)[t];
        xs[1 + 4 * t + 0] = v.x; xs[1 + 4 * t + 1] = v.y;
        xs[1 + 4 * t + 2] = v.z; xs[1 + 4 * t + 3] = v.w;
    }
    if (t == 0) { xs[0] = 0.f; xs[FIN + 1] = 0.f; }
    if (t < HIDN) { y1s[t] = 0.f; y1s[(FIN + 1) * HIDN + t] = 0.f; }

    // pack conv2 weights into f32x2 channel pairs
    for (int idx = t; idx < HIDN * 24; idx += 128) {
        int o = idx / 24, r = idx % 24, tap = r >> 3, i2 = r & 7;
        w2p[idx] = make_float2(w2[o * 48 + (2 * i2) * 3 + tap],
                               w2[o * 48 + (2 * i2 + 1) * 3 + tap]);
    }

    const int ci = t & 15;  // constant per thread across the conv1 strided loop
    const float cw0 = __ldg(w1 + ci * 3 + 0);
    const float cw1 = __ldg(w1 + ci * 3 + 1);
    const float cw2 = __ldg(w1 + ci * 3 + 2);
    const float cb  = __ldg(b1 + ci);
    __syncthreads();

    // ---- conv1 + relu -> y1s[p+1][ci] ----
    for (int idx = t; idx < FIN * HIDN; idx += 128) {
        int p = idx >> 4;  // 0..499
        float v = fmaf(cw0, xs[p], fmaf(cw1, xs[p + 1], fmaf(cw2, xs[p + 2], cb)));
        y1s[(p + 1) * HIDN + ci] = fmaxf(v, 0.f);
    }
    __syncthreads();

    // ---- conv2 + relu + max over positions ----
    const int o      = t & 15;
    const int set    = t >> 4;           // 0..7
    const int pstart = set * 63;
    const int pend   = (pstart + 63 < FIN) ? (pstart + 63) : FIN;  // last set = 59

    ull wv[24];
    {
        const ull* wp = reinterpret_cast<const ull*>(w2p) + o * 24;
        #pragma unroll
        for (int j = 0; j < 24; j++) wv[j] = wp[j];
    }

    ull c0[8], c1[8], c2[8];
    float mx = -3.4e38f;

    auto loadcol = [&](ull (&c)[8], int P) {
        const ulonglong2* cp = reinterpret_cast<const ulonglong2*>(y1s + P * HIDN);
        ulonglong2 a = cp[0], b = cp[1], cc = cp[2], d = cp[3];
        c[0] = a.x; c[1] = a.y; c[2] = b.x; c[3] = b.y;
        c[4] = cc.x; c[5] = cc.y; c[6] = d.x; c[7] = d.y;
    };
    auto step = [&](ull (&A)[8], ull (&B)[8], ull (&C)[8]) {
        ull a0 = 0, a1 = 0, a2 = 0;  // 3 independent chains
        #pragma unroll
        for (int j = 0; j < 8; j++) {
            a0 = fma2(wv[j],      A[j], a0);
            a1 = fma2(wv[8 + j],  B[j], a1);
            a2 = fma2(wv[16 + j], C[j], a2);
        }
        ull sv = add2(add2(a0, a1), a2);
        float lo = __uint_as_float((unsigned)(sv & 0xffffffffull));
        float hi = __uint_as_float((unsigned)(sv >> 32));
        mx = fmaxf(mx, lo + hi);
    };

    // position p needs smem columns p, p+1, p+2 (1-based layout)
    loadcol(c0, pstart);
    loadcol(c1, pstart + 1);
    int p = pstart;
    const int ntrip = (pend - pstart) / 3;
    for (int it = 0; it < ntrip; it++) {
        loadcol(c2, p + 2); step(c0, c1, c2);
        loadcol(c0, p + 3); step(c1, c2, c0);
        loadcol(c1, p + 4); step(c2, c0, c1);
        p += 3;
    }
    for (; p < pend; p++) {  // scalar remainder (<=2 positions)
        float s = 0.f;
        #pragma unroll
        for (int j = 0; j < 24; j++) {
            float2 w = w2p[o * 24 + j];
            int tap = j >> 3, i2 = j & 7;
            s += w.x * y1s[(p + tap) * HIDN + 2 * i2]
               + w.y * y1s[(p + tap) * HIDN + 2 * i2 + 1];
        }
        mx = fmaxf(mx, s);
    }

    // cross-set max reduction; relu(b + max) == max_p relu(b + s_p)
    redbuf[t] = mx;
    __syncthreads();
    if (t < HIDN) {
        float m = redbuf[t];
        #pragma unroll
        for (int s2 = 1; s2 < 8; s2++) m = fmaxf(m, redbuf[t + 16 * s2]);
        g_h0[node * HIDN + t] = fmaxf(m + __ldg(b2 + t), 0.f);
    }
}

// ---------------- GCN kernels ----------------
__global__ void zero_kernel() {
    int i = blockIdx.x * blockDim.x + threadIdx.x;
    if (i < NN * HIDN) g_acc1[i] = 0.f;
    if (i < NN * 4)    g_acc2[i] = 0.f;
    if (i < NN)        g_deg[i]  = 0;
}

__global__ void deg_kernel(const int* __restrict__ ei) {
    int e = blockIdx.x * blockDim.x + threadIdx.x;
    if (e < NE) atomicAdd(&g_deg[ei[NE + e]], 1);
}

// m1[v][j] = dinv[v] * sum_i h0[v][i] * W1[i][j]
__global__ void m1_kernel(const float* __restrict__ w) {
    int gid = blockIdx.x * blockDim.x + threadIdx.x;
    if (gid >= NN * HIDN) return;
    int v = gid >> 4, j = gid & 15;
    float dinv = rsqrtf((float)g_deg[v] + 1.0f);   // +1 self-loop
    if (j == 0) g_dinv[v] = dinv;
    float s = 0.f;
    #pragma unroll
    for (int i = 0; i < HIDN; i++)
        s = fmaf(g_h0[v * HIDN + i], __ldg(w + i * HIDN + j), s);
    g_m1[gid] = s * dinv;
}

__global__ void scatter1_kernel(const int* __restrict__ ei) {
    int e = blockIdx.x * blockDim.x + threadIdx.x;
    if (e >= NE) return;
    int s = ei[e], d = ei[NE + e];
    const float4* m = reinterpret_cast<const float4*>(g_m1 + s * HIDN);
    float4 v0 = m[0], v1 = m[1], v2 = m[2], v3 = m[3];
    float* a = g_acc1 + d * HIDN;
    red4(a, v0); red4(a + 4, v1); red4(a + 8, v2); red4(a + 12, v3);
}

// out1 = relu(dinv*(acc1+m1) + b1g); m2 = (out1 @ W2g) * dinv
__global__ void out1m2_kernel(const float* __restrict__ gb1, const float* __restrict__ gw2) {
    int v = blockIdx.x * blockDim.x + threadIdx.x;
    if (v >= NN) return;
    float dinv = g_dinv[v];
    const float4* a = reinterpret_cast<const float4*>(g_acc1 + v * HIDN);
    const float4* m = reinterpret_cast<const float4*>(g_m1 + v * HIDN);
    float o1[HIDN];
    #pragma unroll
    for (int q = 0; q < 4; q++) {
        float4 av = a[q], mv = m[q];
        o1[4 * q + 0] = fmaxf(dinv * (av.x + mv.x) + __ldg(gb1 + 4 * q + 0), 0.f);
        o1[4 * q + 1] = fmaxf(dinv * (av.y + mv.y) + __ldg(gb1 + 4 * q + 1), 0.f);
        o1[4 * q + 2] = fmaxf(dinv * (av.z + mv.z) + __ldg(gb1 + 4 * q + 2), 0.f);
        o1[4 * q + 3] = fmaxf(dinv * (av.w + mv.w) + __ldg(gb1 + 4 * q + 3), 0.f);
    }
    float s0 = 0.f, s1 = 0.f, s2 = 0.f;
    #pragma unroll
    for (int j = 0; j < HIDN; j++) {
        float h = o1[j];
        s0 = fmaf(h, __ldg(gw2 + j * 3 + 0), s0);
        s1 = fmaf(h, __ldg(gw2 + j * 3 + 1), s1);
        s2 = fmaf(h, __ldg(gw2 + j * 3 + 2), s2);
    }
    reinterpret_cast<float4*>(g_m2)[v] = make_float4(s0 * dinv, s1 * dinv, s2 * dinv, 0.f);
}

__global__ void scatter2_kernel(const int* __restrict__ ei) {
    int e = blockIdx.x * blockDim.x + threadIdx.x;
    if (e >= NE) return;
    int s = ei[e], d = ei[NE + e];
    float4 v = reinterpret_cast<const float4*>(g_m2)[s];
    red4(g_acc2 + d * 4, v);
}

__global__ void final_kernel(const float* __restrict__ gb2, float* __restrict__ out) {
    int v = blockIdx.x * blockDim.x + threadIdx.x;
    if (v >= NN) return;
    float dinv = g_dinv[v];
    float4 a = reinterpret_cast<const float4*>(g_acc2)[v];
    float4 m = reinterpret_cast<const float4*>(g_m2)[v];
    float z0 = dinv * (a.x + m.x) + __ldg(gb2 + 0);
    float z1 = dinv * (a.y + m.y) + __ldg(gb2 + 1);
    float z2 = dinv * (a.z + m.z) + __ldg(gb2 + 2);
    float mx = fmaxf(z0, fmaxf(z1, z2));
    float l = logf(expf(z0 - mx) + expf(z1 - mx) + expf(z2 - mx));
    out[v * 3 + 0] = z0 - mx - l;
    out[v * 3 + 1] = z1 - mx - l;
    out[v * 3 + 2] = z2 - mx - l;
}

// ---------------- launch ----------------
extern "C" void kernel_launch(void* const* d_in, const int* in_sizes, int n_in,
                              void* d_out, int out_size) {
    const float* x   = (const float*)d_in[0];
    const float* c1w = (const float*)d_in[1];
    const float* c1b = (const float*)d_in[2];
    const float* c2w = (const float*)d_in[3];
    const float* c2b = (const float*)d_in[4];
    const float* g1w = (const float*)d_in[5];
    const float* g1b = (const float*)d_in[6];
    const float* g2w = (const float*)d_in[7];
    const float* g2b = (const float*)d_in[8];
    const int*   ei  = (const int*)d_in[9];
    float* out = (float*)d_out;

    zero_kernel<<<(NN * HIDN + 255) / 256, 256>>>();
    conv_fused_kernel<<<NN, 128>>>(x, c1w, c1b, c2w, c2b);
    deg_kernel<<<(NE + 255) / 256, 256>>>(ei);
    m1_kernel<<<(NN * HIDN + 255) / 256, 256>>>(g1w);
    scatter1_kernel<<<(NE + 255) / 256, 256>>>(ei);
    out1m2_kernel<<<(NN + 127) / 128, 128>>>(g1b, g2w);
    scatter2_kernel<<<(NE + 255) / 256, 256>>>(ei);
    final_kernel<<<(NN + 127) / 128, 128>>>(g2b, out);
}

// round 11
// speedup vs baseline: 2.1584x; 2.1439x over previous
#include <cuda_runtime.h>
#include <cuda_bf16.h>
#include <math.h>
#include <stdint.h>

#define NN   30000
#define FIN  500
#define HIDN 16
#define NE   960000

// ---------------- scratch (device globals: no allocation allowed) ----------------
__device__ float g_h0[NN * HIDN];
__device__ float g_m1[NN * HIDN];
__device__ float g_acc1[NN * HIDN];
__device__ float g_m2[NN * 4];
__device__ float g_acc2[NN * 4];
__device__ float g_dinv[NN];
__device__ int   g_deg[NN];

__device__ __forceinline__ void red4(float* p, float4 v) {
    asm volatile("red.global.add.v4.f32 [%0], {%1,%2,%3,%4};"
                 :: "l"(p), "f"(v.x), "f"(v.y), "f"(v.z), "f"(v.w) : "memory");
}

__device__ __forceinline__ void mma_bf16(float d[4],
                                         uint32_t a0, uint32_t a1, uint32_t a2, uint32_t a3,
                                         uint32_t b0, uint32_t b1) {
    asm volatile(
        "mma.sync.aligned.m16n8k16.row.col.f32.bf16.bf16.f32 "
        "{%0,%1,%2,%3}, {%4,%5,%6,%7}, {%8,%9}, {%0,%1,%2,%3};"
        : "+f"(d[0]), "+f"(d[1]), "+f"(d[2]), "+f"(d[3])
        : "r"(a0), "r"(a1), "r"(a2), "r"(a3), "r"(b0), "r"(b1));
}

// split fp32 pair -> bf16x2 hi + bf16x2 lo (lo = residual), low half = first arg
__device__ __forceinline__ void split2(float v0, float v1, uint32_t& h, uint32_t& l) {
    __nv_bfloat162 hh = __float22bfloat162_rn(make_float2(v0, v1));  // .x=v0 (low)
    h = *reinterpret_cast<uint32_t*>(&hh);
    float h0 = __uint_as_float(h << 16);
    float h1 = __uint_as_float(h & 0xffff0000u);
    __nv_bfloat162 ll = __float22bfloat162_rn(make_float2(v0 - h0, v1 - h1));
    l = *reinterpret_cast<uint32_t*>(&ll);
}

// ---------------- conv1+relu+conv2+relu+maxpool via HMMA (mma.sync bf16) ----------
// One block = 4 nodes sequentially, 128 threads (4 warps).
// y1 (conv1 output, relu'd) stored row-major [pos+1][16] as bf16 hi/lo in smem;
// A row p of the conv2 im2col GEMM is then the contiguous window y1mem[p*16 .. +48).
// D[512,16] = A[512,48] x B[48,16] via m16n8k16, 3-product bf16 split, fp32 acc.
// Per warp: 8 M-tiles of 16 rows; running max in registers; rows p>=500 masked.
__global__ void __launch_bounds__(128) conv_mma_kernel(
    const float* __restrict__ x,
    const float* __restrict__ w1, const float* __restrict__ b1,
    const float* __restrict__ w2, const float* __restrict__ b2)
{
    __shared__ __align__(16) uint16_t y1h[514 * 16];
    __shared__ __align__(16) uint16_t y1l[514 * 16];
    __shared__ __align__(16) float xs[516];
    __shared__ float redbuf[64];

    const int t    = threadIdx.x;
    const int wid  = t >> 5;
    const int lane = t & 31;

    // ---- one-time: zero pad rows (P=0 and P=501..513) and xs pads ----
    if (t < 16) { y1h[t] = 0; y1l[t] = 0; }
    for (int i = 501 * 16 + t; i < 514 * 16; i += 128) { y1h[i] = 0; y1l[i] = 0; }
    if (t < 2)  xs[t] = 0.f;
    for (int i = 502 + t; i < 516; i += 128) xs[i] = 0.f;

    // ---- B fragments (per thread, same across warps) ----
    // K-tile kt == tap; b0: i=(lane&3)*2, b1 holds k+8; n = nt*8 + lane/4
    uint32_t bh[3][2][2], bl[3][2][2];
    {
        const int bn = lane >> 2;
        const int bi = (lane & 3) * 2;
        #pragma unroll
        for (int kt = 0; kt < 3; kt++)
            #pragma unroll
            for (int nt = 0; nt < 2; nt++) {
                const int n = nt * 8 + bn;
                #pragma unroll
                for (int rr = 0; rr < 2; rr++) {
                    const int i = bi + rr * 8;
                    float wa = __ldg(w2 + n * 48 + i * 3 + kt);
                    float wb = __ldg(w2 + n * 48 + (i + 1) * 3 + kt);
                    split2(wa, wb, bh[kt][nt][rr], bl[kt][nt][rr]);
                }
            }
    }

    // ---- conv1 weights for this thread's channel pair ----
    const int i2 = t & 7;                  // channel pair index
    const int ch = 2 * i2;
    const float u00 = __ldg(w1 + ch * 3 + 0), u01 = __ldg(w1 + ch * 3 + 1), u02 = __ldg(w1 + ch * 3 + 2);
    const float u10 = __ldg(w1 + ch * 3 + 3), u11 = __ldg(w1 + ch * 3 + 4), u12 = __ldg(w1 + ch * 3 + 5);
    const float ub0 = __ldg(b1 + ch), ub1 = __ldg(b1 + ch + 1);

    // A fragment base (elems): row p = tile*16 + lane/4 (+8), col k = kt*16 + (lane&3)*2 (+8)
    const uint32_t abase = (uint32_t)((lane >> 2) * 16 + (lane & 3) * 2);

    const int nbase = blockIdx.x * 4;
    for (int rep = 0; rep < 4; rep++) {
        const int node = nbase + rep;

        if (t < 125) {
            float4 v = reinterpret_cast<const float4*>(x + (size_t)node * FIN)[t];
            xs[2 + 4 * t] = v.x; xs[3 + 4 * t] = v.y;
            xs[4 + 4 * t] = v.z; xs[5 + 4 * t] = v.w;
        }
        __syncthreads();   // xs ready; prev iter's redbuf fully consumed

        // ---- conv1 + relu -> y1 hi/lo (bf16), rows P = p+1 ----
        for (int p = (t >> 3); p < FIN; p += 16) {
            const float xa = xs[p + 1], xb = xs[p + 2], xc = xs[p + 3];
            const float y0 = fmaxf(fmaf(u00, xa, fmaf(u01, xb, fmaf(u02, xc, ub0))), 0.f);
            const float y1 = fmaxf(fmaf(u10, xa, fmaf(u11, xb, fmaf(u12, xc, ub1))), 0.f);
            uint32_t h, l;
            split2(y0, y1, h, l);
            const uint32_t eo = (uint32_t)((p + 1) * 16 + ch);
            *reinterpret_cast<uint32_t*>(y1h + eo) = h;
            *reinterpret_cast<uint32_t*>(y1l + eo) = l;
        }
        __syncthreads();   // y1 ready

        // ---- GEMM + running max ----
        float mx[2][2] = {{-3.4e38f, -3.4e38f}, {-3.4e38f, -3.4e38f}};  // [nt][even/odd col]
        #pragma unroll 1
        for (int j = 0; j < 8; j++) {
            const int tile = wid * 8 + j;
            const uint32_t aoff = (uint32_t)(tile * 16 * 16) + abase;
            float d0[4] = {0.f, 0.f, 0.f, 0.f};
            float d1[4] = {0.f, 0.f, 0.f, 0.f};
            #pragma unroll
            for (int kt = 0; kt < 3; kt++) {
                const uint32_t ea = aoff + (uint32_t)(kt * 16);
                const uint32_t ah0 = *reinterpret_cast<const uint32_t*>(y1h + ea);
                const uint32_t ah1 = *reinterpret_cast<const uint32_t*>(y1h + ea + 128);
                const uint32_t ah2 = *reinterpret_cast<const uint32_t*>(y1h + ea + 8);
                const uint32_t ah3 = *reinterpret_cast<const uint32_t*>(y1h + ea + 136);
                const uint32_t al0 = *reinterpret_cast<const uint32_t*>(y1l + ea);
                const uint32_t al1 = *reinterpret_cast<const uint32_t*>(y1l + ea + 128);
                const uint32_t al2 = *reinterpret_cast<const uint32_t*>(y1l + ea + 8);
                const uint32_t al3 = *reinterpret_cast<const uint32_t*>(y1l + ea + 136);
                // 3-product split, interleave the two independent N-tile chains
                mma_bf16(d0, ah0, ah1, ah2, ah3, bh[kt][0][0], bh[kt][0][1]);
                mma_bf16(d1, ah0, ah1, ah2, ah3, bh[kt][1][0], bh[kt][1][1]);
                mma_bf16(d0, al0, al1, al2, al3, bh[kt][0][0], bh[kt][0][1]);
                mma_bf16(d1, al0, al1, al2, al3, bh[kt][1][0], bh[kt][1][1]);
                mma_bf16(d0, ah0, ah1, ah2, ah3, bl[kt][0][0], bl[kt][0][1]);
                mma_bf16(d1, ah0, ah1, ah2, ah3, bl[kt][1][0], bl[kt][1][1]);
            }
            if (tile != 31) {
                mx[0][0] = fmaxf(mx[0][0], fmaxf(d0[0], d0[2]));
                mx[0][1] = fmaxf(mx[0][1], fmaxf(d0[1], d0[3]));
                mx[1][0] = fmaxf(mx[1][0], fmaxf(d1[0], d1[2]));
                mx[1][1] = fmaxf(mx[1][1], fmaxf(d1[1], d1[3]));
            } else if (lane < 16) {
                // rows 496..499 live in d0/d1 of lanes 0..15; rows 500..511 masked
                mx[0][0] = fmaxf(mx[0][0], d0[0]);
                mx[0][1] = fmaxf(mx[0][1], d0[1]);
                mx[1][0] = fmaxf(mx[1][0], d1[0]);
                mx[1][1] = fmaxf(mx[1][1], d1[1]);
            }
        }

        // butterfly max across lanes sharing (lane&3): xor 4, 8, 16
        #pragma unroll
        for (int off = 4; off <= 16; off <<= 1) {
            #pragma unroll
            for (int nt = 0; nt < 2; nt++) {
                mx[nt][0] = fmaxf(mx[nt][0], __shfl_xor_sync(0xffffffffu, mx[nt][0], off));
                mx[nt][1] = fmaxf(mx[nt][1], __shfl_xor_sync(0xffffffffu, mx[nt][1], off));
            }
        }
        if (lane < 4) {
            redbuf[wid * 16 + 2 * lane]         = mx[0][0];
            redbuf[wid * 16 + 2 * lane + 1]     = mx[0][1];
            redbuf[wid * 16 + 8 + 2 * lane]     = mx[1][0];
            redbuf[wid * 16 + 8 + 2 * lane + 1] = mx[1][1];
        }
        __syncthreads();   // redbuf ready
        if (t < 16) {
            float m = fmaxf(fmaxf(redbuf[t], redbuf[16 + t]),
                            fmaxf(redbuf[32 + t], redbuf[48 + t]));
            g_h0[node * HIDN + t] = fmaxf(m + __ldg(b2 + t), 0.f);
        }
        // next iteration's first __syncthreads orders redbuf reads vs rewrites
    }
}

// ---------------- GCN kernels (unchanged from passing 671us version) ----------------
__global__ void zero_kernel() {
    int i = blockIdx.x * blockDim.x + threadIdx.x;
    if (i < NN * HIDN) g_acc1[i] = 0.f;
    if (i < NN * 4)    g_acc2[i] = 0.f;
    if (i < NN)        g_deg[i]  = 0;
}

__global__ void deg_kernel(const int* __restrict__ ei) {
    int e = blockIdx.x * blockDim.x + threadIdx.x;
    if (e < NE) atomicAdd(&g_deg[ei[NE + e]], 1);
}

__global__ void m1_kernel(const float* __restrict__ w) {
    int gid = blockIdx.x * blockDim.x + threadIdx.x;
    if (gid >= NN * HIDN) return;
    int v = gid >> 4, j = gid & 15;
    float dinv = rsqrtf((float)g_deg[v] + 1.0f);
    if (j == 0) g_dinv[v] = dinv;
    float s = 0.f;
    #pragma unroll
    for (int i = 0; i < HIDN; i++)
        s = fmaf(g_h0[v * HIDN + i], __ldg(w + i * HIDN + j), s);
    g_m1[gid] = s * dinv;
}

__global__ void scatter1_kernel(const int* __restrict__ ei) {
    int e = blockIdx.x * blockDim.x + threadIdx.x;
    if (e >= NE) return;
    int s = ei[e], d = ei[NE + e];
    const float4* m = reinterpret_cast<const float4*>(g_m1 + s * HIDN);
    float4 v0 = m[0], v1 = m[1], v2 = m[2], v3 = m[3];
    float* a = g_acc1 + d * HIDN;
    red4(a, v0); red4(a + 4, v1); red4(a + 8, v2); red4(a + 12, v3);
}

__global__ void out1m2_kernel(const float* __restrict__ gb1, const float* __restrict__ gw2) {
    int v = blockIdx.x * blockDim.x + threadIdx.x;
    if (v >= NN) return;
    float dinv = g_dinv[v];
    const float4* a = reinterpret_cast<const float4*>(g_acc1 + v * HIDN);
    const float4* m = reinterpret_cast<const float4*>(g_m1 + v * HIDN);
    float o1[HIDN];
    #pragma unroll
    for (int q = 0; q < 4; q++) {
        float4 av = a[q], mv = m[q];
        o1[4 * q + 0] = fmaxf(dinv * (av.x + mv.x) + __ldg(gb1 + 4 * q + 0), 0.f);
        o1[4 * q + 1] = fmaxf(dinv * (av.y + mv.y) + __ldg(gb1 + 4 * q + 1), 0.f);
        o1[4 * q + 2] = fmaxf(dinv * (av.z + mv.z) + __ldg(gb1 + 4 * q + 2), 0.f);
        o1[4 * q + 3] = fmaxf(dinv * (av.w + mv.w) + __ldg(gb1 + 4 * q + 3), 0.f);
    }
    float s0 = 0.f, s1 = 0.f, s2 = 0.f;
    #pragma unroll
    for (int j = 0; j < HIDN; j++) {
        float h = o1[j];
        s0 = fmaf(h, __ldg(gw2 + j * 3 + 0), s0);
        s1 = fmaf(h, __ldg(gw2 + j * 3 + 1), s1);
        s2 = fmaf(h, __ldg(gw2 + j * 3 + 2), s2);
    }
    reinterpret_cast<float4*>(g_m2)[v] = make_float4(s0 * dinv, s1 * dinv, s2 * dinv, 0.f);
}

__global__ void scatter2_kernel(const int* __restrict__ ei) {
    int e = blockIdx.x * blockDim.x + threadIdx.x;
    if (e >= NE) return;
    int s = ei[e], d = ei[NE + e];
    float4 v = reinterpret_cast<const float4*>(g_m2)[s];
    red4(g_acc2 + d * 4, v);
}

__global__ void final_kernel(const float* __restrict__ gb2, float* __restrict__ out) {
    int v = blockIdx.x * blockDim.x + threadIdx.x;
    if (v >= NN) return;
    float dinv = g_dinv[v];
    float4 a = reinterpret_cast<const float4*>(g_acc2)[v];
    float4 m = reinterpret_cast<const float4*>(g_m2)[v];
    float z0 = dinv * (a.x + m.x) + __ldg(gb2 + 0);
    float z1 = dinv * (a.y + m.y) + __ldg(gb2 + 1);
    float z2 = dinv * (a.z + m.z) + __ldg(gb2 + 2);
    float mx = fmaxf(z0, fmaxf(z1, z2));
    float l = logf(expf(z0 - mx) + expf(z1 - mx) + expf(z2 - mx));
    out[v * 3 + 0] = z0 - mx - l;
    out[v * 3 + 1] = z1 - mx - l;
    out[v * 3 + 2] = z2 - mx - l;
}

// ---------------- launch ----------------
extern "C" void kernel_launch(void* const* d_in, const int* in_sizes, int n_in,
                              void* d_out, int out_size) {
    const float* x   = (const float*)d_in[0];
    const float* c1w = (const float*)d_in[1];
    const float* c1b = (const float*)d_in[2];
    const float* c2w = (const float*)d_in[3];
    const float* c2b = (const float*)d_in[4];
    const float* g1w = (const float*)d_in[5];
    const float* g1b = (const float*)d_in[6];
    const float* g2w = (const float*)d_in[7];
    const float* g2b = (const float*)d_in[8];
    const int*   ei  = (const int*)d_in[9];
    float* out = (float*)d_out;

    zero_kernel<<<(NN * HIDN + 255) / 256, 256>>>();
    conv_mma_kernel<<<NN / 4, 128>>>(x, c1w, c1b, c2w, c2b);
    deg_kernel<<<(NE + 255) / 256, 256>>>(ei);
    m1_kernel<<<(NN * HIDN + 255) / 256, 256>>>(g1w);
    scatter1_kernel<<<(NE + 255) / 256, 256>>>(ei);
    out1m2_kernel<<<(NN + 127) / 128, 128>>>(g1b, g2w);
    scatter2_kernel<<<(NE + 255) / 256, 256>>>(ei);
    final_kernel<<<(NN + 127) / 128, 128>>>(g2b, out);
}